// round 3
// baseline (speedup 1.0000x reference)
#include <cuda_runtime.h>
#include <math.h>

#define B 32
#define T 1024
#define NIN 64
#define NRES 2048
#define NOUT 64
#define CAP 320            // max padded nnz per row (mean 204.8, sd 13.6)
#define SCAN_CTAS 128
#define ROWS_PER_CTA 16    // 128 * 16 = 2048; TWO warps per row (1024 thr/CTA)

struct __align__(8) Pair { float w; int k; };

// Static device scratch (sanctioned by harness rules).
__device__ Pair  g_pairs[NRES][CAP];                      // ~5.2 MB
__device__ int   g_cnt[NRES];
__device__ float g_U[(size_t)T * NRES * B];               // 256 MB: [t][n][b]
__device__ float g_S[(size_t)(T + 1) * NRES * B];         // 256 MB: [t][n][b], g_S[0]=0
__device__ unsigned long long g_bar;

// ---------------------------------------------------------------------------
// Init: zero h_0 and the barrier counter (runs every launch/replay).
// ---------------------------------------------------------------------------
__global__ void init_kernel() {
    int tid = blockIdx.x * blockDim.x + threadIdx.x;
    if (tid == 0) g_bar = 0ULL;
    for (int i = tid; i < NRES * B; i += gridDim.x * blockDim.x)
        g_S[i] = 0.f;
}

// ---------------------------------------------------------------------------
// Build sparse ELL of W_res: one warp per row, k-ascending deterministic order.
// Pads each row's nnz to a multiple of 16 with zero-weight entries.
// ---------------------------------------------------------------------------
__global__ void build_sparse_kernel(const float* __restrict__ W_res) {
    int warp = threadIdx.x >> 5;
    int lane = threadIdx.x & 31;
    int n = blockIdx.x * 8 + warp;            // grid 256 x 256 threads
    if (n >= NRES) return;
    const float* row = W_res + (size_t)n * NRES;
    int base = 0;
    for (int c = 0; c < NRES; c += 32) {
        float w = row[c + lane];
        unsigned mask = __ballot_sync(0xffffffffu, w != 0.f);
        int pos = base + __popc(mask & ((1u << lane) - 1u));
        if (w != 0.f && pos < CAP) {
            g_pairs[n][pos].w = w;
            g_pairs[n][pos].k = c + lane;
        }
        base += __popc(mask);
    }
    if (lane == 0) {
        int cnt = base < CAP ? base : CAP;
        int cnt16 = (cnt + 15) & ~15;          // pad to multiple of 16
        if (cnt16 > CAP) cnt16 = CAP;
        g_cnt[n] = cnt16;
        for (int j = cnt; j < cnt16; j++) {
            g_pairs[n][j].w = 0.f;
            g_pairs[n][j].k = 0;
        }
    }
}

// ---------------------------------------------------------------------------
// U[t][n][b] = b_res[n] + sum_d x[b][t][d] * W_in[n][d]
// ---------------------------------------------------------------------------
__global__ __launch_bounds__(256) void u_kernel(const float* __restrict__ x,
                                                const float* __restrict__ W_in,
                                                const float* __restrict__ b_res) {
    __shared__ float s_w[64 * 68];   // [d][n_l], stride 68
    __shared__ float s_x[64 * 33];   // [d][b],  stride 33
    int tid = threadIdx.x;
    int n0 = blockIdx.x * 64;
    int t0 = blockIdx.y * 16;

    for (int i = tid; i < 64 * 64; i += 256) {
        int nl = i >> 6, d = i & 63;
        s_w[d * 68 + nl] = W_in[(size_t)(n0 + nl) * NIN + d];
    }

    int warp = tid >> 5, lane = tid & 31;
    float bias[8];
#pragma unroll
    for (int i = 0; i < 8; i++) bias[i] = __ldg(b_res + n0 + warp * 8 + i);

    for (int tt = 0; tt < 16; tt++) {
        int t = t0 + tt;
        __syncthreads();
        for (int i = tid; i < B * 64; i += 256) {
            int b = i >> 6, d = i & 63;
            s_x[d * 33 + b] = x[((size_t)b * T + t) * NIN + d];
        }
        __syncthreads();

        float acc[8];
#pragma unroll
        for (int i = 0; i < 8; i++) acc[i] = 0.f;
#pragma unroll 4
        for (int d = 0; d < 64; d++) {
            float xv = s_x[d * 33 + lane];
            float4 w0 = *(const float4*)&s_w[d * 68 + warp * 8];
            float4 w1 = *(const float4*)&s_w[d * 68 + warp * 8 + 4];
            acc[0] = fmaf(w0.x, xv, acc[0]);
            acc[1] = fmaf(w0.y, xv, acc[1]);
            acc[2] = fmaf(w0.z, xv, acc[2]);
            acc[3] = fmaf(w0.w, xv, acc[3]);
            acc[4] = fmaf(w1.x, xv, acc[4]);
            acc[5] = fmaf(w1.y, xv, acc[5]);
            acc[6] = fmaf(w1.z, xv, acc[6]);
            acc[7] = fmaf(w1.w, xv, acc[7]);
        }
        float* out = g_U + ((size_t)t * NRES + n0 + warp * 8) * B + lane;
#pragma unroll
        for (int i = 0; i < 8; i++) out[(size_t)i * B] = acc[i] + bias[i];
    }
}

// ---------------------------------------------------------------------------
// Persistent scan: 128 CTAs x 1024 threads, TWO warps per row.
// Warp pair (even=half 0, odd=half 1) splits the row's nnz. Within a warp:
// group g = lane>>3 picks nnz j+g; bq = (lane&7)*4 picks a float4 of batch.
// Each LDG.128 fetches 4 cache lines per warp. Cross-group reduce via
// shfl.bfly(8,16); odd warp deposits partial in smem; even warp combines,
// applies u + tanh, stores float4.
// ---------------------------------------------------------------------------
__global__ __launch_bounds__(1024, 1) void scan_kernel() {
    __shared__ Pair   s_pairs[ROWS_PER_CTA][CAP];   // 40 KB
    __shared__ int    s_cnt[ROWS_PER_CTA];
    __shared__ float4 s_acc[ROWS_PER_CTA][8];       // 2 KB partials from odd warps
    int tid  = threadIdx.x;
    int warp = tid >> 5;          // 0..31
    int lane = tid & 31;
    int r    = warp >> 1;         // row within CTA, 0..15
    int half = warp & 1;          // nnz half
    int n0   = blockIdx.x * ROWS_PER_CTA;
    int n    = n0 + r;

    // even warps stage their row's (padded) pairs
    if (half == 0) {
        int cnt = g_cnt[n];
        if (lane == 0) s_cnt[r] = cnt;
        for (int j = lane; j < cnt; j += 32)
            s_pairs[r][j] = g_pairs[n][j];
    }
    __syncthreads();

    const int g  = lane >> 3;        // nnz subgroup 0..3
    const int bq = (lane & 7) * 4;   // batch quad offset
    const Pair* __restrict__ pp = s_pairs[r];
    const int half_len = s_cnt[r] >> 1;       // multiple of 8
    const int j_begin  = half * half_len;
    const int j_end    = j_begin + half_len;

    for (int t = 0; t < T; t++) {
        const float* __restrict__ hp = g_S + (size_t)t * NRES * B;
        float*       __restrict__ hn = g_S + (size_t)(t + 1) * NRES * B;
        const float* __restrict__ up = g_U + (size_t)t * NRES * B;

        // issue u load early (only even-warp lanes 0-7 consume it)
        float4 u = make_float4(0.f, 0.f, 0.f, 0.f);
        if (half == 0 && g == 0) u = *(const float4*)(up + (size_t)n * B + bq);

        float4 acc = make_float4(0.f, 0.f, 0.f, 0.f);
#pragma unroll 4
        for (int j = j_begin; j < j_end; j += 4) {
            Pair p = pp[j + g];                                  // LDS.64 bcast
            float4 h = __ldg((const float4*)(hp + (size_t)p.k * B + bq));
            acc.x = fmaf(p.w, h.x, acc.x);
            acc.y = fmaf(p.w, h.y, acc.y);
            acc.z = fmaf(p.w, h.z, acc.z);
            acc.w = fmaf(p.w, h.w, acc.w);
        }
        // reduce the 4 nnz groups (xor 8, 16) -> lanes 0-7 hold quad sums
#pragma unroll
        for (int ofs = 8; ofs <= 16; ofs <<= 1) {
            acc.x += __shfl_xor_sync(0xffffffffu, acc.x, ofs);
            acc.y += __shfl_xor_sync(0xffffffffu, acc.y, ofs);
            acc.z += __shfl_xor_sync(0xffffffffu, acc.z, ofs);
            acc.w += __shfl_xor_sync(0xffffffffu, acc.w, ofs);
        }
        if (half == 1 && g == 0) s_acc[r][lane] = acc;
        __syncthreads();
        if (half == 0 && g == 0) {
            float4 po = s_acc[r][lane];
            float4 hv;
            hv.x = tanhf(u.x + acc.x + po.x);
            hv.y = tanhf(u.y + acc.y + po.y);
            hv.z = tanhf(u.z + acc.z + po.z);
            hv.w = tanhf(u.w + acc.w + po.w);
            *(float4*)(hn + (size_t)n * B + bq) = hv;
        }

        // ---- grid barrier (monotonic ULL counter, reset by init_kernel) ----
        __syncthreads();
        __threadfence();                           // release stores (all threads)
        if (tid == 0) {
            atomicAdd(&g_bar, 1ULL);
            unsigned long long target = (unsigned long long)(t + 1) * SCAN_CTAS;
            while (*(volatile unsigned long long*)&g_bar < target) { }
            __threadfence();                       // acquire everyone's writes
        }
        __syncthreads();
    }
}

// ---------------------------------------------------------------------------
// y[b][t][o] = b_out[o] + sum_n S[t+1][n][b] * W_out[o][n]
// ---------------------------------------------------------------------------
__global__ __launch_bounds__(256) void readout_kernel(const float* __restrict__ W_out,
                                                      const float* __restrict__ b_out,
                                                      float* __restrict__ y) {
    __shared__ float s_wo[128 * 68];   // [n_l][o], stride 68
    int tid = threadIdx.x, warp = tid >> 5, lane = tid & 31;
    int t = blockIdx.x;

    float acc[8];
#pragma unroll
    for (int i = 0; i < 8; i++) acc[i] = 0.f;

    const float* sp_base = g_S + (size_t)(t + 1) * NRES * B;

    for (int ch = 0; ch < NRES / 128; ch++) {
        __syncthreads();
        for (int i = tid; i < 128 * 64; i += 256) {
            int nl = i & 127, o = i >> 7;
            s_wo[nl * 68 + o] = W_out[(size_t)o * NRES + ch * 128 + nl];
        }
        __syncthreads();
        const float* sp = sp_base + (size_t)ch * 128 * B;
#pragma unroll 4
        for (int nl = 0; nl < 128; nl++) {
            float sv = __ldg(sp + nl * B + lane);
            float4 w0 = *(const float4*)&s_wo[nl * 68 + warp * 8];
            float4 w1 = *(const float4*)&s_wo[nl * 68 + warp * 8 + 4];
            acc[0] = fmaf(w0.x, sv, acc[0]);
            acc[1] = fmaf(w0.y, sv, acc[1]);
            acc[2] = fmaf(w0.z, sv, acc[2]);
            acc[3] = fmaf(w0.w, sv, acc[3]);
            acc[4] = fmaf(w1.x, sv, acc[4]);
            acc[5] = fmaf(w1.y, sv, acc[5]);
            acc[6] = fmaf(w1.z, sv, acc[6]);
            acc[7] = fmaf(w1.w, sv, acc[7]);
        }
    }
#pragma unroll
    for (int i = 0; i < 8; i++) {
        int o = warp * 8 + i;
        y[((size_t)lane * T + t) * NOUT + o] = acc[i] + __ldg(b_out + o);
    }
}

// ---------------------------------------------------------------------------
extern "C" void kernel_launch(void* const* d_in, const int* in_sizes, int n_in,
                              void* d_out, int out_size) {
    const float* x     = (const float*)d_in[0];  // [32,1024,64]
    const float* W_in  = (const float*)d_in[1];  // [2048,64]
    const float* W_res = (const float*)d_in[2];  // [2048,2048]
    const float* b_res = (const float*)d_in[3];  // [2048]
    const float* W_out = (const float*)d_in[4];  // [64,2048]
    const float* b_out = (const float*)d_in[5];  // [64]
    float* y = (float*)d_out;                    // [32,1024,64]

    init_kernel<<<64, 256>>>();
    build_sparse_kernel<<<NRES / 8, 256>>>(W_res);
    dim3 gu(NRES / 64, T / 16);
    u_kernel<<<gu, 256>>>(x, W_in, b_res);
    scan_kernel<<<SCAN_CTAS, 1024>>>();
    readout_kernel<<<T, 256>>>(W_out, b_out, y);
}